// round 1
// baseline (speedup 1.0000x reference)
#include <cuda_runtime.h>
#include <cuda_bf16.h>
#include <math.h>

#define N_BATCH 4
#define LQ      5448
#define LSP     5440
#define DMODEL  256
#define DFFN    1024
#define NHEADS  8
#define DHEAD   32
#define NVT     8
#define NALLVT  600
#define TTOK    (N_BATCH * LQ)   // 21792

// -------------------- scratch (no allocation allowed) --------------------
__device__ float g_q    [(size_t)TTOK * DMODEL];
__device__ float g_vin  [(size_t)TTOK * DMODEL];
__device__ float g_value[(size_t)TTOK * DMODEL];
__device__ float g_off  [(size_t)TTOK * DMODEL];
__device__ float g_attn [(size_t)TTOK * 128];
__device__ float g_samp [(size_t)TTOK * DMODEL];
__device__ float g_src2 [(size_t)TTOK * DMODEL];
__device__ float g_x    [(size_t)TTOK * DMODEL];
__device__ float g_h    [(size_t)TTOK * DFFN];
__device__ float g_y    [(size_t)TTOK * DMODEL];

// -------------------- build q = [src+pos ; sel_vt], vin = [src ; sel_vt] --------------------
__global__ void build_qv_kernel(const float* __restrict__ src, const float* __restrict__ pos,
                                const float* __restrict__ sel,
                                float* __restrict__ q, float* __restrict__ vin)
{
    size_t gid = (size_t)blockIdx.x * 256 + threadIdx.x;
    if (gid >= (size_t)TTOK * DMODEL) return;
    int d = (int)(gid & 255);
    size_t t = gid >> 8;
    int n = (int)(t / LQ);
    int i = (int)(t % LQ);
    float qv, vv;
    if (i < LSP) {
        size_t si = ((size_t)n * LSP + i) * DMODEL + d;
        vv = src[si];
        qv = vv + pos[si];
    } else {
        size_t si = ((size_t)n * NVT + (i - LSP)) * DMODEL + d;
        vv = sel[si];
        qv = vv;
    }
    q[gid]   = qv;
    vin[gid] = vv;
}

// -------------------- generic SGEMM: out[T,N] = A[T,K] * W[N,K]^T + bias --------------------
// BM=BN=64, BK=16, 256 threads, each thread 4x4.
__global__ void sgemm_tn(const float* __restrict__ A, const float* __restrict__ W,
                         const float* __restrict__ bias, float* __restrict__ out,
                         int T, int K, int Nout, int relu, const unsigned char* __restrict__ mask)
{
    __shared__ float As[16][64];
    __shared__ float Ws[16][64];
    const int bm  = blockIdx.y * 64;
    const int bn  = blockIdx.x * 64;
    const int tid = threadIdx.x;
    const int tx  = tid & 15;
    const int ty  = tid >> 4;
    const int lrow = tid >> 2;         // 0..63
    const int lcol = (tid & 3) << 2;   // 0,4,8,12

    float acc[4][4];
#pragma unroll
    for (int i = 0; i < 4; i++)
#pragma unroll
        for (int j = 0; j < 4; j++) acc[i][j] = 0.f;

    for (int k0 = 0; k0 < K; k0 += 16) {
        float4 av = make_float4(0.f, 0.f, 0.f, 0.f);
        int ar = bm + lrow;
        if (ar < T) av = *reinterpret_cast<const float4*>(A + (size_t)ar * K + k0 + lcol);
        As[lcol + 0][lrow] = av.x;
        As[lcol + 1][lrow] = av.y;
        As[lcol + 2][lrow] = av.z;
        As[lcol + 3][lrow] = av.w;

        float4 wv = make_float4(0.f, 0.f, 0.f, 0.f);
        int wr = bn + lrow;
        if (wr < Nout) wv = *reinterpret_cast<const float4*>(W + (size_t)wr * K + k0 + lcol);
        Ws[lcol + 0][lrow] = wv.x;
        Ws[lcol + 1][lrow] = wv.y;
        Ws[lcol + 2][lrow] = wv.z;
        Ws[lcol + 3][lrow] = wv.w;

        __syncthreads();
#pragma unroll
        for (int k = 0; k < 16; k++) {
            float4 a = *reinterpret_cast<const float4*>(&As[k][ty * 4]);
            float4 w = *reinterpret_cast<const float4*>(&Ws[k][tx * 4]);
            acc[0][0] += a.x * w.x; acc[0][1] += a.x * w.y; acc[0][2] += a.x * w.z; acc[0][3] += a.x * w.w;
            acc[1][0] += a.y * w.x; acc[1][1] += a.y * w.y; acc[1][2] += a.y * w.z; acc[1][3] += a.y * w.w;
            acc[2][0] += a.z * w.x; acc[2][1] += a.z * w.y; acc[2][2] += a.z * w.z; acc[2][3] += a.z * w.w;
            acc[3][0] += a.w * w.x; acc[3][1] += a.w * w.y; acc[3][2] += a.w * w.z; acc[3][3] += a.w * w.w;
        }
        __syncthreads();
    }

#pragma unroll
    for (int i = 0; i < 4; i++) {
        int row = bm + ty * 4 + i;
        if (row >= T) continue;
        bool zero = (mask != nullptr) && (mask[row] != 0);
#pragma unroll
        for (int j = 0; j < 4; j++) {
            int col = bn + tx * 4 + j;
            if (col >= Nout) continue;
            float v = acc[i][j] + bias[col];
            if (relu) v = fmaxf(v, 0.f);
            if (zero) v = 0.f;
            out[(size_t)row * Nout + col] = v;
        }
    }
}

// -------------------- deformable sampling: warp per (token, head) --------------------
__global__ void msdeform_sample_kernel(const float* __restrict__ value,
                                       const float* __restrict__ logits,
                                       const float* __restrict__ off,
                                       const float* __restrict__ ref,
                                       float* __restrict__ out)
{
    const int nq   = blockIdx.x;          // n*LQ + q
    const int n    = nq / LQ;
    const int m    = threadIdx.x >> 5;    // head
    const int lane = threadIdx.x & 31;

    // softmax over 16 logits for this head (lanes 0..15 hold one each)
    const float* lg = logits + (size_t)nq * 128 + m * 16;
    float v = (lane < 16) ? lg[lane] : -1e30f;
    float mx = v;
#pragma unroll
    for (int o = 16; o > 0; o >>= 1) mx = fmaxf(mx, __shfl_xor_sync(0xffffffffu, mx, o));
    float e = (lane < 16) ? __expf(v - mx) : 0.f;
    float sm = e;
#pragma unroll
    for (int o = 16; o > 0; o >>= 1) sm += __shfl_xor_sync(0xffffffffu, sm, o);
    float wgt = e / sm;

    // offsets: 32 floats per head = 16 samples x (dx,dy); lane holds one component
    float offv = off[(size_t)nq * DMODEL + m * 32 + lane];
    // reference points: 4 levels x (x,y); lanes 0..7
    float refv = (lane < 8) ? ref[(size_t)nq * 8 + lane] : 0.f;

    const float* vb = value + (size_t)n * LQ * DMODEL + m * 32 + lane;

    const int HH[4] = {64, 32, 16, 8};
    const int WW[4] = {64, 32, 16, 8};
    const int ST[4] = {0, 4096, 5120, 5376};

    float acc = 0.f;
#pragma unroll
    for (int s = 0; s < 16; s++) {
        const int l = s >> 2;
        float dx = __shfl_sync(0xffffffffu, offv, 2 * s);
        float dy = __shfl_sync(0xffffffffu, offv, 2 * s + 1);
        float rx = __shfl_sync(0xffffffffu, refv, 2 * l);
        float ry = __shfl_sync(0xffffffffu, refv, 2 * l + 1);
        float ws = __shfl_sync(0xffffffffu, wgt, s);
        const int H = HH[l], W = WW[l], st = ST[l];

        // W,H are powers of two: (rx + dx/W)*W - 0.5 == rx*W + dx - 0.5 exactly
        float x = rx * (float)W + dx - 0.5f;
        float y = ry * (float)H + dy - 0.5f;
        float xf = floorf(x), yf = floorf(y);
        int x0 = (int)xf, y0 = (int)yf;
        float wx = x - xf, wy = y - yf;

        float w00 = (1.f - wx) * (1.f - wy);
        float w10 = wx * (1.f - wy);
        float w01 = (1.f - wx) * wy;
        float w11 = wx * wy;

        float samp = 0.f;
        if (x0 >= 0 && x0 < W && y0 >= 0 && y0 < H)
            samp += w00 * vb[(size_t)(st + y0 * W + x0) * DMODEL];
        if (x0 + 1 >= 0 && x0 + 1 < W && y0 >= 0 && y0 < H)
            samp += w10 * vb[(size_t)(st + y0 * W + x0 + 1) * DMODEL];
        if (x0 >= 0 && x0 < W && y0 + 1 >= 0 && y0 + 1 < H)
            samp += w01 * vb[(size_t)(st + (y0 + 1) * W + x0) * DMODEL];
        if (x0 + 1 >= 0 && x0 + 1 < W && y0 + 1 >= 0 && y0 + 1 < H)
            samp += w11 * vb[(size_t)(st + (y0 + 1) * W + x0 + 1) * DMODEL];

        acc += ws * samp;
    }
    out[(size_t)nq * DMODEL + m * 32 + lane] = acc;
}

// -------------------- add + LayerNorm (optionally scattered to final output) --------------------
__global__ void add_ln_kernel(const float* __restrict__ a, const float* __restrict__ b,
                              const float* __restrict__ g, const float* __restrict__ beta,
                              float* __restrict__ out, int scatter)
{
    const int t = blockIdx.x;
    const int d = threadIdx.x;
    const int lane = d & 31, wid = d >> 5;

    float v = a[(size_t)t * DMODEL + d] + b[(size_t)t * DMODEL + d];

    __shared__ float red[8];
    float s = v;
#pragma unroll
    for (int o = 16; o > 0; o >>= 1) s += __shfl_xor_sync(0xffffffffu, s, o);
    if (lane == 0) red[wid] = s;
    __syncthreads();
    float mean;
    {
        float tot = 0.f;
        if (d == 0) {
#pragma unroll
            for (int i = 0; i < 8; i++) tot += red[i];
            red[0] = tot;
        }
        __syncthreads();
        mean = red[0] * (1.f / 256.f);
    }
    __syncthreads();

    float xc = v - mean;
    s = xc * xc;
#pragma unroll
    for (int o = 16; o > 0; o >>= 1) s += __shfl_xor_sync(0xffffffffu, s, o);
    if (lane == 0) red[wid] = s;
    __syncthreads();
    float var;
    {
        float tot = 0.f;
        if (d == 0) {
#pragma unroll
            for (int i = 0; i < 8; i++) tot += red[i];
            red[0] = tot;
        }
        __syncthreads();
        var = red[0] * (1.f / 256.f);
    }

    float r = g[d] * xc * rsqrtf(var + 1e-5f) + beta[d];

    float* dst;
    if (!scatter) {
        dst = out + (size_t)t * DMODEL;
    } else {
        int n = t / LQ, i = t % LQ;
        if (i < LSP)
            dst = out + ((size_t)n * LSP + i) * DMODEL;
        else
            dst = out + ((size_t)N_BATCH * LSP + (size_t)N_BATCH * NALLVT) * DMODEL
                      + ((size_t)n * NVT + (i - LSP)) * DMODEL;
    }
    dst[d] = r;
}

// -------------------- launch --------------------
extern "C" void kernel_launch(void* const* d_in, const int* in_sizes, int n_in,
                              void* d_out, int out_size)
{
    const float* src  = (const float*)d_in[0];
    const float* pos  = (const float*)d_in[1];
    const float* ref  = (const float*)d_in[2];
    const unsigned char* mask = (const unsigned char*)d_in[5];
    const float* all_vt = (const float*)d_in[6];
    const float* sel_vt = (const float*)d_in[7];
    const float* Wv = (const float*)d_in[8];   const float* bv  = (const float*)d_in[9];
    const float* Wo = (const float*)d_in[10];  const float* bo  = (const float*)d_in[11];
    const float* Wa = (const float*)d_in[12];  const float* ba  = (const float*)d_in[13];
    const float* Wp = (const float*)d_in[14];  const float* bp  = (const float*)d_in[15];
    const float* g1 = (const float*)d_in[16];  const float* be1 = (const float*)d_in[17];
    const float* W1 = (const float*)d_in[18];  const float* bf1 = (const float*)d_in[19];
    const float* W2 = (const float*)d_in[20];  const float* bf2 = (const float*)d_in[21];
    const float* g2 = (const float*)d_in[22];  const float* be2 = (const float*)d_in[23];
    float* out = (float*)d_out;

    float *q, *vin, *value, *off, *attn, *samp, *src2, *x, *h, *y;
    cudaGetSymbolAddress((void**)&q,     g_q);
    cudaGetSymbolAddress((void**)&vin,   g_vin);
    cudaGetSymbolAddress((void**)&value, g_value);
    cudaGetSymbolAddress((void**)&off,   g_off);
    cudaGetSymbolAddress((void**)&attn,  g_attn);
    cudaGetSymbolAddress((void**)&samp,  g_samp);
    cudaGetSymbolAddress((void**)&src2,  g_src2);
    cudaGetSymbolAddress((void**)&x,     g_x);
    cudaGetSymbolAddress((void**)&h,     g_h);
    cudaGetSymbolAddress((void**)&y,     g_y);

    const int T = TTOK;

    // 1) build q / v_in
    build_qv_kernel<<<TTOK, 256>>>(src, pos, sel_vt, q, vin);

    dim3 blk(256);
    const int gm = (T + 63) / 64;

    // 2) value = vin @ Wv^T + bv (masked)
    sgemm_tn<<<dim3(256 / 64, gm), blk>>>(vin, Wv, bv, value, T, 256, 256, 0, mask);
    // 3) off = q @ Wo^T + bo
    sgemm_tn<<<dim3(256 / 64, gm), blk>>>(q, Wo, bo, off, T, 256, 256, 0, nullptr);
    // 4) attn logits = q @ Wa^T + ba
    sgemm_tn<<<dim3(128 / 64, gm), blk>>>(q, Wa, ba, attn, T, 256, 128, 0, nullptr);

    // 5) deformable sampling (softmax fused)
    msdeform_sample_kernel<<<TTOK, 256>>>(value, attn, off, ref, samp);

    // 6) src2 = samp @ Wp^T + bp
    sgemm_tn<<<dim3(256 / 64, gm), blk>>>(samp, Wp, bp, src2, T, 256, 256, 0, nullptr);

    // 7) x = LN(vin + src2)
    add_ln_kernel<<<TTOK, 256>>>(vin, src2, g1, be1, x, 0);

    // 8) h = relu(x @ W1^T + bf1)
    sgemm_tn<<<dim3(DFFN / 64, gm), blk>>>(x, W1, bf1, h, T, 256, DFFN, 1, nullptr);
    // 9) y = h @ W2^T + bf2
    sgemm_tn<<<dim3(256 / 64, gm), blk>>>(h, W2, bf2, y, T, DFFN, 256, 0, nullptr);

    // 10) out = LN(x + y) scattered into [spatial | all_vt | vt] layout
    add_ln_kernel<<<TTOK, 256>>>(x, y, g2, be2, out, 1);

    // 11) all_vt passthrough
    cudaMemcpyAsync(out + (size_t)N_BATCH * LSP * DMODEL, all_vt,
                    (size_t)N_BATCH * NALLVT * DMODEL * sizeof(float),
                    cudaMemcpyDeviceToDevice, 0);
}

// round 4
// speedup vs baseline: 1.5462x; 1.5462x over previous
#include <cuda_runtime.h>
#include <cuda_bf16.h>
#include <math.h>
#include <stdint.h>

#define N_BATCH 4
#define LQ      5448
#define LSP     5440
#define DMODEL  256
#define DFFN    1024
#define NVT     8
#define NALLVT  600
#define TTOK    (N_BATCH * LQ)   // 21792

// -------------------- scratch (no allocation allowed) --------------------
__device__ float g_q    [(size_t)TTOK * DMODEL];
__device__ float g_vin  [(size_t)TTOK * DMODEL];
__device__ float g_value[(size_t)TTOK * DMODEL];
__device__ float g_off  [(size_t)TTOK * DMODEL];
__device__ float g_attn [(size_t)TTOK * 128];
__device__ float g_samp [(size_t)TTOK * DMODEL];
__device__ float g_src2 [(size_t)TTOK * DMODEL];
__device__ float g_x    [(size_t)TTOK * DMODEL];
__device__ float g_h    [(size_t)TTOK * DFFN];
__device__ float g_y    [(size_t)TTOK * DMODEL];

// ==================== helpers ====================
__device__ __forceinline__ uint32_t smem_u32(const void* p) {
    return (uint32_t)__cvta_generic_to_shared(p);
}
__device__ __forceinline__ void cp_async16(uint32_t dst, const void* src, int src_size) {
    asm volatile("cp.async.cg.shared.global [%0], [%1], 16, %2;\n"
                 :: "r"(dst), "l"(src), "r"(src_size));
}
__device__ __forceinline__ void cp_async_commit() {
    asm volatile("cp.async.commit_group;" ::: "memory");
}
template<int N> __device__ __forceinline__ void cp_async_wait() {
    asm volatile("cp.async.wait_group %0;" :: "n"(N) : "memory");
}

// split fp32 into tf32-hi (13 low mantissa bits cleared) + residual
__device__ __forceinline__ void tf32_split(float x, uint32_t& h, uint32_t& l) {
    uint32_t u = __float_as_uint(x) & 0xffffe000u;
    h = u;
    l = __float_as_uint(x - __uint_as_float(u));
}

__device__ __forceinline__ void mma8(float* d, const uint32_t* a, const uint32_t* b) {
    asm volatile(
        "mma.sync.aligned.m16n8k8.row.col.f32.tf32.tf32.f32 "
        "{%0,%1,%2,%3}, {%4,%5,%6,%7}, {%8,%9}, {%0,%1,%2,%3};"
        : "+f"(d[0]), "+f"(d[1]), "+f"(d[2]), "+f"(d[3])
        : "r"(a[0]), "r"(a[1]), "r"(a[2]), "r"(a[3]), "r"(b[0]), "r"(b[1]));
}

// ==================== tensor-core GEMM: out[T,N] = A[T,K]*W[N,K]^T + bias ====================
// CTA tile 128x64, BK=16, 8 warps (4 M x 2 N), warp tile 32x32, double-buffered cp.async.
#define BM 128
#define BN 64
#define BK 16
#define ASTR 20   // row stride in floats (16 + 4 pad, keeps 16B alignment & banks clean)
#define BSTR 20

__global__ void __launch_bounds__(256)
gemm_mma(const float* __restrict__ A, const float* __restrict__ W,
         const float* __restrict__ bias, float* __restrict__ out,
         int T, int K, int Nout, int relu, const unsigned char* __restrict__ mask)
{
    __shared__ float As[2][BM * ASTR];
    __shared__ float Bs[2][BN * BSTR];

    const int tid  = threadIdx.x;
    const int wid  = tid >> 5;
    const int lane = tid & 31;
    const int bm = blockIdx.x * BM;
    const int bn = blockIdx.y * BN;
    const int warpM = wid & 3;          // 0..3
    const int warpN = wid >> 2;         // 0..1
    const int mbase = warpM * 32;
    const int nbase = warpN * 32;
    const int gq = lane >> 2;           // 0..7
    const int tg = lane & 3;            // 0..3

    float acc[2][4][4];
#pragma unroll
    for (int mi = 0; mi < 2; mi++)
#pragma unroll
        for (int ni = 0; ni < 4; ni++)
#pragma unroll
            for (int r = 0; r < 4; r++) acc[mi][ni][r] = 0.f;

    auto load = [&](int k0, int buf) {
#pragma unroll
        for (int i = 0; i < 2; i++) {
            int c = tid + 256 * i;
            int row = c >> 2;
            int kc = (c & 3) << 2;
            int gr = bm + row;
            int grc = gr < T ? gr : T - 1;
            cp_async16(smem_u32(&As[buf][row * ASTR + kc]),
                       A + (size_t)grc * K + k0 + kc, gr < T ? 16 : 0);
        }
        {
            int row = tid >> 2;
            int kc = (tid & 3) << 2;
            cp_async16(smem_u32(&Bs[buf][row * BSTR + kc]),
                       W + (size_t)(bn + row) * K + k0 + kc, 16);
        }
        cp_async_commit();
    };

    const int nch = K >> 4;   // K / 16
    load(0, 0);

    for (int i = 0; i < nch; i++) {
        cp_async_wait<0>();
        __syncthreads();
        if (i + 1 < nch) load((i + 1) << 4, (i + 1) & 1);

        const float* Ab = As[i & 1];
        const float* Bb = Bs[i & 1];
#pragma unroll
        for (int kk = 0; kk < 2; kk++) {
            const int k0 = kk * 8;
            uint32_t ah[2][4], al[2][4];
#pragma unroll
            for (int mi = 0; mi < 2; mi++) {
                int r = mbase + mi * 16 + gq;
                float a0 = Ab[(r)     * ASTR + k0 + tg];
                float a1 = Ab[(r + 8) * ASTR + k0 + tg];
                float a2 = Ab[(r)     * ASTR + k0 + tg + 4];
                float a3 = Ab[(r + 8) * ASTR + k0 + tg + 4];
                tf32_split(a0, ah[mi][0], al[mi][0]);
                tf32_split(a1, ah[mi][1], al[mi][1]);
                tf32_split(a2, ah[mi][2], al[mi][2]);
                tf32_split(a3, ah[mi][3], al[mi][3]);
            }
            uint32_t bh[4][2], bl[4][2];
#pragma unroll
            for (int ni = 0; ni < 4; ni++) {
                int n = nbase + ni * 8 + gq;
                float b0 = Bb[n * BSTR + k0 + tg];
                float b1 = Bb[n * BSTR + k0 + tg + 4];
                tf32_split(b0, bh[ni][0], bl[ni][0]);
                tf32_split(b1, bh[ni][1], bl[ni][1]);
            }
#pragma unroll
            for (int mi = 0; mi < 2; mi++)
#pragma unroll
                for (int ni = 0; ni < 4; ni++) {
                    mma8(acc[mi][ni], ah[mi], bh[ni]);   // hi*hi
                    mma8(acc[mi][ni], al[mi], bh[ni]);   // lo*hi
                    mma8(acc[mi][ni], ah[mi], bl[ni]);   // hi*lo
                }
        }
        __syncthreads();
    }

    // ---- epilogue ----
#pragma unroll
    for (int mi = 0; mi < 2; mi++) {
        int row0 = bm + mbase + mi * 16 + gq;
#pragma unroll
        for (int half = 0; half < 2; half++) {
            int row = row0 + half * 8;
            if (row >= T) continue;
            bool zero = (mask != nullptr) && (mask[row] != 0);
            float* orow = out + (size_t)row * Nout + bn + nbase;
#pragma unroll
            for (int ni = 0; ni < 4; ni++) {
                int col = ni * 8 + tg * 2;
                float2 v;
                v.x = acc[mi][ni][half * 2 + 0] + bias[bn + nbase + col];
                v.y = acc[mi][ni][half * 2 + 1] + bias[bn + nbase + col + 1];
                if (relu) { v.x = fmaxf(v.x, 0.f); v.y = fmaxf(v.y, 0.f); }
                if (zero) { v.x = 0.f; v.y = 0.f; }
                *reinterpret_cast<float2*>(orow + col) = v;
            }
        }
    }
}

// -------------------- build q = [src+pos ; sel_vt], vin = [src ; sel_vt] --------------------
__global__ void build_qv_kernel(const float* __restrict__ src, const float* __restrict__ pos,
                                const float* __restrict__ sel,
                                float* __restrict__ q, float* __restrict__ vin)
{
    size_t gid = (size_t)blockIdx.x * 256 + threadIdx.x;
    if (gid >= (size_t)TTOK * DMODEL) return;
    int d = (int)(gid & 255);
    size_t t = gid >> 8;
    int n = (int)(t / LQ);
    int i = (int)(t % LQ);
    float qv, vv;
    if (i < LSP) {
        size_t si = ((size_t)n * LSP + i) * DMODEL + d;
        vv = src[si];
        qv = vv + pos[si];
    } else {
        size_t si = ((size_t)n * NVT + (i - LSP)) * DMODEL + d;
        vv = sel[si];
        qv = vv;
    }
    q[gid]   = qv;
    vin[gid] = vv;
}

// -------------------- deformable sampling: warp per (token, head) --------------------
__global__ void msdeform_sample_kernel(const float* __restrict__ value,
                                       const float* __restrict__ logits,
                                       const float* __restrict__ off,
                                       const float* __restrict__ ref,
                                       float* __restrict__ out)
{
    const int nq   = blockIdx.x;          // n*LQ + q
    const int n    = nq / LQ;
    const int m    = threadIdx.x >> 5;    // head
    const int lane = threadIdx.x & 31;

    const float* lg = logits + (size_t)nq * 128 + m * 16;
    float v = (lane < 16) ? lg[lane] : -1e30f;
    float mx = v;
#pragma unroll
    for (int o = 16; o > 0; o >>= 1) mx = fmaxf(mx, __shfl_xor_sync(0xffffffffu, mx, o));
    float e = (lane < 16) ? __expf(v - mx) : 0.f;
    float sm = e;
#pragma unroll
    for (int o = 16; o > 0; o >>= 1) sm += __shfl_xor_sync(0xffffffffu, sm, o);
    float wgt = e / sm;

    float offv = off[(size_t)nq * DMODEL + m * 32 + lane];
    float refv = (lane < 8) ? ref[(size_t)nq * 8 + lane] : 0.f;

    const float* vb = value + (size_t)n * LQ * DMODEL + m * 32 + lane;

    const int HH[4] = {64, 32, 16, 8};
    const int WW[4] = {64, 32, 16, 8};
    const int ST[4] = {0, 4096, 5120, 5376};

    float acc = 0.f;
#pragma unroll
    for (int s = 0; s < 16; s++) {
        const int l = s >> 2;
        float dx = __shfl_sync(0xffffffffu, offv, 2 * s);
        float dy = __shfl_sync(0xffffffffu, offv, 2 * s + 1);
        float rx = __shfl_sync(0xffffffffu, refv, 2 * l);
        float ry = __shfl_sync(0xffffffffu, refv, 2 * l + 1);
        float ws = __shfl_sync(0xffffffffu, wgt, s);
        const int H = HH[l], W = WW[l], st = ST[l];

        float x = rx * (float)W + dx - 0.5f;
        float y = ry * (float)H + dy - 0.5f;
        float xf = floorf(x), yf = floorf(y);
        int x0 = (int)xf, y0 = (int)yf;
        float wx = x - xf, wy = y - yf;

        float w00 = (1.f - wx) * (1.f - wy);
        float w10 = wx * (1.f - wy);
        float w01 = (1.f - wx) * wy;
        float w11 = wx * wy;

        float samp = 0.f;
        if (x0 >= 0 && x0 < W && y0 >= 0 && y0 < H)
            samp += w00 * vb[(size_t)(st + y0 * W + x0) * DMODEL];
        if (x0 + 1 >= 0 && x0 + 1 < W && y0 >= 0 && y0 < H)
            samp += w10 * vb[(size_t)(st + y0 * W + x0 + 1) * DMODEL];
        if (x0 >= 0 && x0 < W && y0 + 1 >= 0 && y0 + 1 < H)
            samp += w01 * vb[(size_t)(st + (y0 + 1) * W + x0) * DMODEL];
        if (x0 + 1 >= 0 && x0 + 1 < W && y0 + 1 >= 0 && y0 + 1 < H)
            samp += w11 * vb[(size_t)(st + (y0 + 1) * W + x0 + 1) * DMODEL];

        acc += ws * samp;
    }
    out[(size_t)nq * DMODEL + m * 32 + lane] = acc;
}

// -------------------- add + LayerNorm (optionally scattered to final output) --------------------
__global__ void add_ln_kernel(const float* __restrict__ a, const float* __restrict__ b,
                              const float* __restrict__ g, const float* __restrict__ beta,
                              float* __restrict__ out, int scatter)
{
    const int t = blockIdx.x;
    const int d = threadIdx.x;
    const int lane = d & 31, wid = d >> 5;

    float v = a[(size_t)t * DMODEL + d] + b[(size_t)t * DMODEL + d];

    __shared__ float red[8];
    float s = v;
#pragma unroll
    for (int o = 16; o > 0; o >>= 1) s += __shfl_xor_sync(0xffffffffu, s, o);
    if (lane == 0) red[wid] = s;
    __syncthreads();
    float mean;
    {
        if (d == 0) {
            float tot = 0.f;
#pragma unroll
            for (int i = 0; i < 8; i++) tot += red[i];
            red[0] = tot;
        }
        __syncthreads();
        mean = red[0] * (1.f / 256.f);
    }
    __syncthreads();

    float xc = v - mean;
    s = xc * xc;
#pragma unroll
    for (int o = 16; o > 0; o >>= 1) s += __shfl_xor_sync(0xffffffffu, s, o);
    if (lane == 0) red[wid] = s;
    __syncthreads();
    float var;
    {
        if (d == 0) {
            float tot = 0.f;
#pragma unroll
            for (int i = 0; i < 8; i++) tot += red[i];
            red[0] = tot;
        }
        __syncthreads();
        var = red[0] * (1.f / 256.f);
    }

    float r = g[d] * xc * rsqrtf(var + 1e-5f) + beta[d];

    float* dst;
    if (!scatter) {
        dst = out + (size_t)t * DMODEL;
    } else {
        int n = t / LQ, i = t % LQ;
        if (i < LSP)
            dst = out + ((size_t)n * LSP + i) * DMODEL;
        else
            dst = out + ((size_t)N_BATCH * LSP + (size_t)N_BATCH * NALLVT) * DMODEL
                      + ((size_t)n * NVT + (i - LSP)) * DMODEL;
    }
    dst[d] = r;
}

// -------------------- launch --------------------
extern "C" void kernel_launch(void* const* d_in, const int* in_sizes, int n_in,
                              void* d_out, int out_size)
{
    const float* src  = (const float*)d_in[0];
    const float* pos  = (const float*)d_in[1];
    const float* ref  = (const float*)d_in[2];
    const unsigned char* mask = (const unsigned char*)d_in[5];
    const float* all_vt = (const float*)d_in[6];
    const float* sel_vt = (const float*)d_in[7];
    const float* Wv = (const float*)d_in[8];   const float* bv  = (const float*)d_in[9];
    const float* Wo = (const float*)d_in[10];  const float* bo  = (const float*)d_in[11];
    const float* Wa = (const float*)d_in[12];  const float* ba  = (const float*)d_in[13];
    const float* Wp = (const float*)d_in[14];  const float* bp  = (const float*)d_in[15];
    const float* g1 = (const float*)d_in[16];  const float* be1 = (const float*)d_in[17];
    const float* W1 = (const float*)d_in[18];  const float* bf1 = (const float*)d_in[19];
    const float* W2 = (const float*)d_in[20];  const float* bf2 = (const float*)d_in[21];
    const float* g2 = (const float*)d_in[22];  const float* be2 = (const float*)d_in[23];
    float* out = (float*)d_out;

    float *q, *vin, *value, *off, *attn, *samp, *src2, *x, *h, *y;
    cudaGetSymbolAddress((void**)&q,     g_q);
    cudaGetSymbolAddress((void**)&vin,   g_vin);
    cudaGetSymbolAddress((void**)&value, g_value);
    cudaGetSymbolAddress((void**)&off,   g_off);
    cudaGetSymbolAddress((void**)&attn,  g_attn);
    cudaGetSymbolAddress((void**)&samp,  g_samp);
    cudaGetSymbolAddress((void**)&src2,  g_src2);
    cudaGetSymbolAddress((void**)&x,     g_x);
    cudaGetSymbolAddress((void**)&h,     g_h);
    cudaGetSymbolAddress((void**)&y,     g_y);

    const int T = TTOK;
    const int TM = (T + BM - 1) / BM;   // 171

    // 1) build q / v_in
    build_qv_kernel<<<TTOK, 256>>>(src, pos, sel_vt, q, vin);

    // 2) value = vin @ Wv^T + bv (masked)
    gemm_mma<<<dim3(TM, 256 / BN), 256>>>(vin, Wv, bv, value, T, 256, 256, 0, mask);
    // 3) off = q @ Wo^T + bo
    gemm_mma<<<dim3(TM, 256 / BN), 256>>>(q, Wo, bo, off, T, 256, 256, 0, nullptr);
    // 4) attn logits = q @ Wa^T + ba
    gemm_mma<<<dim3(TM, 128 / BN), 256>>>(q, Wa, ba, attn, T, 256, 128, 0, nullptr);

    // 5) deformable sampling (softmax fused)
    msdeform_sample_kernel<<<TTOK, 256>>>(value, attn, off, ref, samp);

    // 6) src2 = samp @ Wp^T + bp
    gemm_mma<<<dim3(TM, 256 / BN), 256>>>(samp, Wp, bp, src2, T, 256, 256, 0, nullptr);

    // 7) x = LN(vin + src2)
    add_ln_kernel<<<TTOK, 256>>>(vin, src2, g1, be1, x, 0);

    // 8) h = relu(x @ W1^T + bf1)
    gemm_mma<<<dim3(TM, DFFN / BN), 256>>>(x, W1, bf1, h, T, 256, DFFN, 1, nullptr);
    // 9) y = h @ W2^T + bf2
    gemm_mma<<<dim3(TM, 256 / BN), 256>>>(h, W2, bf2, y, T, 1024, 256, 0, nullptr);

    // 10) out = LN(x + y) scattered into [spatial | all_vt | vt] layout
    add_ln_kernel<<<TTOK, 256>>>(x, y, g2, be2, out, 1);

    // 11) all_vt passthrough
    cudaMemcpyAsync(out + (size_t)N_BATCH * LSP * DMODEL, all_vt,
                    (size_t)N_BATCH * NALLVT * DMODEL * sizeof(float),
                    cudaMemcpyDeviceToDevice, 0);
}

// round 6
// speedup vs baseline: 1.8511x; 1.1972x over previous
#include <cuda_runtime.h>
#include <cuda_bf16.h>
#include <math.h>
#include <stdint.h>

#define N_BATCH 4
#define LQ      5448
#define LSP     5440
#define DMODEL  256
#define DFFN    1024
#define NVT     8
#define NALLVT  600
#define TTOK    (N_BATCH * LQ)   // 21792

// -------------------- scratch (no allocation allowed) --------------------
__device__ uint32_t g_q_pk  [(size_t)TTOK * DMODEL];
__device__ float    g_vin   [(size_t)TTOK * DMODEL];
__device__ uint32_t g_vin_pk[(size_t)TTOK * DMODEL];
__device__ float    g_value [(size_t)TTOK * DMODEL];
__device__ float    g_off   [(size_t)TTOK * DMODEL];
__device__ float    g_attn  [(size_t)TTOK * 128];
__device__ uint32_t g_samp_pk[(size_t)TTOK * DMODEL];
__device__ float    g_src2  [(size_t)TTOK * DMODEL];
__device__ float    g_x     [(size_t)TTOK * DMODEL];
__device__ uint32_t g_x_pk  [(size_t)TTOK * DMODEL];
__device__ uint32_t g_h_pk  [(size_t)TTOK * DFFN];
__device__ float    g_y     [(size_t)TTOK * DMODEL];
// packed weights
__device__ uint32_t g_Wv_pk [256 * 256];
__device__ uint32_t g_Woa_pk[384 * 256];   // [Wo(256) ; Wa(128)] x 256
__device__ uint32_t g_Wp_pk [256 * 256];
__device__ uint32_t g_W1_pk [1024 * 256];
__device__ uint32_t g_W2_pk [256 * 1024];
__device__ float    g_bias_oa[384];

// ==================== helpers ====================
__device__ __forceinline__ uint32_t smem_u32(const void* p) {
    return (uint32_t)__cvta_generic_to_shared(p);
}
__device__ __forceinline__ void cp_async16(uint32_t dst, const void* src, int src_size) {
    asm volatile("cp.async.cg.shared.global [%0], [%1], 16, %2;\n"
                 :: "r"(dst), "l"(src), "r"(src_size));
}
__device__ __forceinline__ void cp_async_commit() {
    asm volatile("cp.async.commit_group;" ::: "memory");
}
template<int N> __device__ __forceinline__ void cp_async_wait() {
    asm volatile("cp.async.wait_group %0;" :: "n"(N) : "memory");
}

// pack fp32 -> (bf16 hi | bf16 lo << 16)
__device__ __forceinline__ uint32_t pack_bf(float x) {
    __nv_bfloat16 h = __float2bfloat16(x);
    float hf = __bfloat162float(h);
    __nv_bfloat16 l = __float2bfloat16(x - hf);
    return (uint32_t)__bfloat16_as_ushort(h) | ((uint32_t)__bfloat16_as_ushort(l) << 16);
}

__device__ __forceinline__ void mma16(float* d, const uint32_t* a, const uint32_t* b) {
    asm volatile(
        "mma.sync.aligned.m16n8k16.row.col.f32.bf16.bf16.f32 "
        "{%0,%1,%2,%3}, {%4,%5,%6,%7}, {%8,%9}, {%0,%1,%2,%3};"
        : "+f"(d[0]), "+f"(d[1]), "+f"(d[2]), "+f"(d[3])
        : "r"(a[0]), "r"(a[1]), "r"(a[2]), "r"(a[3]), "r"(b[0]), "r"(b[1]));
}

// ==================== dual-bf16 tensor-core GEMM ====================
// out[T,Nout] = A[T,K] * W[Nout,K]^T + bias ; A,W packed dual-bf16 words.
// CTA 128x64, BK=16, 8 warps (4M x 2N), warp tile 32x32, double buffered.
#define BM 128
#define BN 64
#define BK 16
#define STR 20    // words per smem row (16 + 4 pad), even => 8B-aligned pairs

__global__ void __launch_bounds__(256)
gemm_bf16(const uint32_t* __restrict__ A, const uint32_t* __restrict__ W,
          const float* __restrict__ bias, int T, int K, int Nout,
          float* __restrict__ outA, int split, float* __restrict__ outB,
          uint32_t* __restrict__ outPk, int relu, const unsigned char* __restrict__ mask)
{
    __shared__ __align__(16) uint32_t As[2][BM * STR];
    __shared__ __align__(16) uint32_t Bs[2][BN * STR];

    const int tid  = threadIdx.x;
    const int wid  = tid >> 5;
    const int lane = tid & 31;
    const int bm = blockIdx.x * BM;
    const int bn = blockIdx.y * BN;
    const int mbase = (wid & 3) * 32;
    const int nbase = (wid >> 2) * 32;
    const int gq = lane >> 2;    // 0..7
    const int tg = lane & 3;     // 0..3

    float acc[2][4][4];
#pragma unroll
    for (int mi = 0; mi < 2; mi++)
#pragma unroll
        for (int ni = 0; ni < 4; ni++)
#pragma unroll
            for (int r = 0; r < 4; r++) acc[mi][ni][r] = 0.f;

    auto load = [&](int k0, int buf) {
#pragma unroll
        for (int i = 0; i < 2; i++) {
            int c = tid + 256 * i;
            int row = c >> 2;
            int kc = (c & 3) << 2;
            int gr = bm + row;
            int grc = gr < T ? gr : T - 1;
            cp_async16(smem_u32(&As[buf][row * STR + kc]),
                       A + (size_t)grc * K + k0 + kc, gr < T ? 16 : 0);
        }
        {
            int row = tid >> 2;
            int kc = (tid & 3) << 2;
            cp_async16(smem_u32(&Bs[buf][row * STR + kc]),
                       W + (size_t)(bn + row) * K + k0 + kc, 16);
        }
        cp_async_commit();
    };

    const int nch = K >> 4;
    load(0, 0);

    for (int i = 0; i < nch; i++) {
        cp_async_wait<0>();
        __syncthreads();
        if (i + 1 < nch) load((i + 1) << 4, (i + 1) & 1);

        const uint32_t* Ab = As[i & 1];
        const uint32_t* Bb = Bs[i & 1];

        uint32_t ah[2][4], al[2][4];
#pragma unroll
        for (int mi = 0; mi < 2; mi++) {
            int r = mbase + mi * 16 + gq;
            uint2 w00 = *reinterpret_cast<const uint2*>(&Ab[(r)     * STR + 2 * tg]);
            uint2 w10 = *reinterpret_cast<const uint2*>(&Ab[(r + 8) * STR + 2 * tg]);
            uint2 w01 = *reinterpret_cast<const uint2*>(&Ab[(r)     * STR + 2 * tg + 8]);
            uint2 w11 = *reinterpret_cast<const uint2*>(&Ab[(r + 8) * STR + 2 * tg + 8]);
            ah[mi][0] = __byte_perm(w00.x, w00.y, 0x5410); al[mi][0] = __byte_perm(w00.x, w00.y, 0x7632);
            ah[mi][1] = __byte_perm(w10.x, w10.y, 0x5410); al[mi][1] = __byte_perm(w10.x, w10.y, 0x7632);
            ah[mi][2] = __byte_perm(w01.x, w01.y, 0x5410); al[mi][2] = __byte_perm(w01.x, w01.y, 0x7632);
            ah[mi][3] = __byte_perm(w11.x, w11.y, 0x5410); al[mi][3] = __byte_perm(w11.x, w11.y, 0x7632);
        }
        uint32_t bh[4][2], bl[4][2];
#pragma unroll
        for (int ni = 0; ni < 4; ni++) {
            int n = nbase + ni * 8 + gq;
            uint2 v0 = *reinterpret_cast<const uint2*>(&Bb[n * STR + 2 * tg]);
            uint2 v1 = *reinterpret_cast<const uint2*>(&Bb[n * STR + 2 * tg + 8]);
            bh[ni][0] = __byte_perm(v0.x, v0.y, 0x5410); bl[ni][0] = __byte_perm(v0.x, v0.y, 0x7632);
            bh[ni][1] = __byte_perm(v1.x, v1.y, 0x5410); bl[ni][1] = __byte_perm(v1.x, v1.y, 0x7632);
        }
#pragma unroll
        for (int mi = 0; mi < 2; mi++)
#pragma unroll
            for (int ni = 0; ni < 4; ni++) {
                mma16(acc[mi][ni], ah[mi], bh[ni]);   // hi*hi
                mma16(acc[mi][ni], ah[mi], bl[ni]);   // hi*lo
                mma16(acc[mi][ni], al[mi], bh[ni]);   // lo*hi
            }
        __syncthreads();
    }

    // ---- epilogue ----
    const int wB = Nout - split;
#pragma unroll
    for (int mi = 0; mi < 2; mi++) {
#pragma unroll
        for (int half = 0; half < 2; half++) {
            int row = bm + mbase + mi * 16 + gq + half * 8;
            if (row >= T) continue;
            bool zero = (mask != nullptr) && (mask[row] != 0);
#pragma unroll
            for (int ni = 0; ni < 4; ni++) {
                int col = nbase + ni * 8 + tg * 2;   // within CTA tile
                int gc = bn + col;
                float vx = acc[mi][ni][half * 2 + 0] + bias[gc];
                float vy = acc[mi][ni][half * 2 + 1] + bias[gc + 1];
                if (relu) { vx = fmaxf(vx, 0.f); vy = fmaxf(vy, 0.f); }
                if (zero) { vx = 0.f; vy = 0.f; }
                if (outPk) {
                    uint2 p; p.x = pack_bf(vx); p.y = pack_bf(vy);
                    *reinterpret_cast<uint2*>(outPk + (size_t)row * Nout + gc) = p;
                }
                if (outA) {
                    if (gc < split) {
                        float2 v; v.x = vx; v.y = vy;
                        *reinterpret_cast<float2*>(outA + (size_t)row * split + gc) = v;
                    } else if (outB) {
                        float2 v; v.x = vx; v.y = vy;
                        *reinterpret_cast<float2*>(outB + (size_t)row * wB + (gc - split)) = v;
                    }
                }
            }
        }
    }
}

// -------------------- weight packing (one launch) --------------------
__global__ void pack_weights(const float* __restrict__ Wv, const float* __restrict__ Wo,
                             const float* __restrict__ Wa, const float* __restrict__ Wp,
                             const float* __restrict__ W1, const float* __restrict__ W2,
                             const float* __restrict__ bo, const float* __restrict__ ba)
{
    int i = blockIdx.x * 256 + threadIdx.x;
    if (i < 65536)            g_Wv_pk[i] = pack_bf(Wv[i]);
    else if (i < 131072)      g_Woa_pk[i - 65536] = pack_bf(Wo[i - 65536]);
    else if (i < 163840)      g_Woa_pk[65536 + (i - 131072)] = pack_bf(Wa[i - 131072]);
    else if (i < 229376)      g_Wp_pk[i - 163840] = pack_bf(Wp[i - 163840]);
    else if (i < 491520)      g_W1_pk[i - 229376] = pack_bf(W1[i - 229376]);
    else if (i < 753664)      g_W2_pk[i - 491520] = pack_bf(W2[i - 491520]);
    else if (i < 753664 + 256) g_bias_oa[i - 753664] = bo[i - 753664];
    else if (i < 753664 + 384) g_bias_oa[i - 753664] = ba[i - 753664 - 256];
}

// -------------------- build q_pk, vin (f32 + pk) --------------------
__global__ void build_qv_kernel(const float* __restrict__ src, const float* __restrict__ pos,
                                const float* __restrict__ sel,
                                uint32_t* __restrict__ q_pk,
                                float* __restrict__ vin, uint32_t* __restrict__ vin_pk)
{
    size_t gid = (size_t)blockIdx.x * 256 + threadIdx.x;
    if (gid >= (size_t)TTOK * DMODEL) return;
    int d = (int)(gid & 255);
    size_t t = gid >> 8;
    int n = (int)(t / LQ);
    int i = (int)(t % LQ);
    float qv, vv;
    if (i < LSP) {
        size_t si = ((size_t)n * LSP + i) * DMODEL + d;
        vv = src[si];
        qv = vv + pos[si];
    } else {
        size_t si = ((size_t)n * NVT + (i - LSP)) * DMODEL + d;
        vv = sel[si];
        qv = vv;
    }
    q_pk[gid]   = pack_bf(qv);
    vin[gid]    = vv;
    vin_pk[gid] = pack_bf(vv);
}

// -------------------- deformable sampling: warp per (token, head) --------------------
__global__ void msdeform_sample_kernel(const float* __restrict__ value,
                                       const float* __restrict__ logits,
                                       const float* __restrict__ off,
                                       const float* __restrict__ ref,
                                       uint32_t* __restrict__ out_pk)
{
    const int nq   = blockIdx.x;
    const int n    = nq / LQ;
    const int m    = threadIdx.x >> 5;
    const int lane = threadIdx.x & 31;

    const float* lg = logits + (size_t)nq * 128 + m * 16;
    float v = (lane < 16) ? lg[lane] : -1e30f;
    float mx = v;
#pragma unroll
    for (int o = 16; o > 0; o >>= 1) mx = fmaxf(mx, __shfl_xor_sync(0xffffffffu, mx, o));
    float e = (lane < 16) ? __expf(v - mx) : 0.f;
    float sm = e;
#pragma unroll
    for (int o = 16; o > 0; o >>= 1) sm += __shfl_xor_sync(0xffffffffu, sm, o);
    float wgt = e / sm;

    float offv = off[(size_t)nq * DMODEL + m * 32 + lane];
    float refv = (lane < 8) ? ref[(size_t)nq * 8 + lane] : 0.f;

    const float* vb = value + (size_t)n * LQ * DMODEL + m * 32 + lane;

    const int HH[4] = {64, 32, 16, 8};
    const int WW[4] = {64, 32, 16, 8};
    const int ST[4] = {0, 4096, 5120, 5376};

    float acc = 0.f;
#pragma unroll
    for (int s = 0; s < 16; s++) {
        const int l = s >> 2;
        float dx = __shfl_sync(0xffffffffu, offv, 2 * s);
        float dy = __shfl_sync(0xffffffffu, offv, 2 * s + 1);
        float rx = __shfl_sync(0xffffffffu, refv, 2 * l);
        float ry = __shfl_sync(0xffffffffu, refv, 2 * l + 1);
        float ws = __shfl_sync(0xffffffffu, wgt, s);
        const int H = HH[l], W = WW[l], st = ST[l];

        float x = rx * (float)W + dx - 0.5f;
        float y = ry * (float)H + dy - 0.5f;
        float xf = floorf(x), yf = floorf(y);
        int x0 = (int)xf, y0 = (int)yf;
        float wx = x - xf, wy = y - yf;

        float w00 = (1.f - wx) * (1.f - wy);
        float w10 = wx * (1.f - wy);
        float w01 = (1.f - wx) * wy;
        float w11 = wx * wy;

        float samp = 0.f;
        if (x0 >= 0 && x0 < W && y0 >= 0 && y0 < H)
            samp += w00 * vb[(size_t)(st + y0 * W + x0) * DMODEL];
        if (x0 + 1 >= 0 && x0 + 1 < W && y0 >= 0 && y0 < H)
            samp += w10 * vb[(size_t)(st + y0 * W + x0 + 1) * DMODEL];
        if (x0 >= 0 && x0 < W && y0 + 1 >= 0 && y0 + 1 < H)
            samp += w01 * vb[(size_t)(st + (y0 + 1) * W + x0) * DMODEL];
        if (x0 + 1 >= 0 && x0 + 1 < W && y0 + 1 >= 0 && y0 + 1 < H)
            samp += w11 * vb[(size_t)(st + (y0 + 1) * W + x0 + 1) * DMODEL];

        acc += ws * samp;
    }
    out_pk[(size_t)nq * DMODEL + m * 32 + lane] = pack_bf(acc);
}

// -------------------- add + LayerNorm --------------------
__global__ void add_ln_kernel(const float* __restrict__ a, const float* __restrict__ b,
                              const float* __restrict__ g, const float* __restrict__ beta,
                              float* __restrict__ out, uint32_t* __restrict__ out_pk, int scatter)
{
    const int t = blockIdx.x;
    const int d = threadIdx.x;
    const int lane = d & 31, wid = d >> 5;

    float v = a[(size_t)t * DMODEL + d] + b[(size_t)t * DMODEL + d];

    __shared__ float red[8];
    float s = v;
#pragma unroll
    for (int o = 16; o > 0; o >>= 1) s += __shfl_xor_sync(0xffffffffu, s, o);
    if (lane == 0) red[wid] = s;
    __syncthreads();
    float mean;
    {
        if (d == 0) {
            float tot = 0.f;
#pragma unroll
            for (int i = 0; i < 8; i++) tot += red[i];
            red[0] = tot;
        }
        __syncthreads();
        mean = red[0] * (1.f / 256.f);
    }
    __syncthreads();

    float xc = v - mean;
    s = xc * xc;
#pragma unroll
    for (int o = 16; o > 0; o >>= 1) s += __shfl_xor_sync(0xffffffffu, s, o);
    if (lane == 0) red[wid] = s;
    __syncthreads();
    float var;
    {
        if (d == 0) {
            float tot = 0.f;
#pragma unroll
            for (int i = 0; i < 8; i++) tot += red[i];
            red[0] = tot;
        }
        __syncthreads();
        var = red[0] * (1.f / 256.f);
    }

    float r = g[d] * xc * rsqrtf(var + 1e-5f) + beta[d];

    if (out_pk) out_pk[(size_t)t * DMODEL + d] = pack_bf(r);

    float* dst;
    if (!scatter) {
        dst = out + (size_t)t * DMODEL;
    } else {
        int n = t / LQ, i = t % LQ;
        if (i < LSP)
            dst = out + ((size_t)n * LSP + i) * DMODEL;
        else
            dst = out + ((size_t)N_BATCH * LSP + (size_t)N_BATCH * NALLVT) * DMODEL
                      + ((size_t)n * NVT + (i - LSP)) * DMODEL;
    }
    dst[d] = r;
}

// -------------------- launch --------------------
extern "C" void kernel_launch(void* const* d_in, const int* in_sizes, int n_in,
                              void* d_out, int out_size)
{
    const float* src  = (const float*)d_in[0];
    const float* pos  = (const float*)d_in[1];
    const float* ref  = (const float*)d_in[2];
    const unsigned char* mask = (const unsigned char*)d_in[5];
    const float* all_vt = (const float*)d_in[6];
    const float* sel_vt = (const float*)d_in[7];
    const float* Wv = (const float*)d_in[8];   const float* bv  = (const float*)d_in[9];
    const float* Wo = (const float*)d_in[10];  const float* bo  = (const float*)d_in[11];
    const float* Wa = (const float*)d_in[12];  const float* ba  = (const float*)d_in[13];
    const float* Wp = (const float*)d_in[14];  const float* bp  = (const float*)d_in[15];
    const float* g1 = (const float*)d_in[16];  const float* be1 = (const float*)d_in[17];
    const float* W1 = (const float*)d_in[18];  const float* bf1 = (const float*)d_in[19];
    const float* W2 = (const float*)d_in[20];  const float* bf2 = (const float*)d_in[21];
    const float* g2 = (const float*)d_in[22];  const float* be2 = (const float*)d_in[23];
    float* out = (float*)d_out;

    uint32_t *q_pk, *vin_pk, *samp_pk, *x_pk, *h_pk;
    uint32_t *Wv_pk, *Woa_pk, *Wp_pk, *W1_pk, *W2_pk;
    float *vin, *value, *off, *attn, *src2, *x, *y, *bias_oa;
    cudaGetSymbolAddress((void**)&q_pk,   g_q_pk);
    cudaGetSymbolAddress((void**)&vin,    g_vin);
    cudaGetSymbolAddress((void**)&vin_pk, g_vin_pk);
    cudaGetSymbolAddress((void**)&value,  g_value);
    cudaGetSymbolAddress((void**)&off,    g_off);
    cudaGetSymbolAddress((void**)&attn,   g_attn);
    cudaGetSymbolAddress((void**)&samp_pk,g_samp_pk);
    cudaGetSymbolAddress((void**)&src2,   g_src2);
    cudaGetSymbolAddress((void**)&x,      g_x);
    cudaGetSymbolAddress((void**)&x_pk,   g_x_pk);
    cudaGetSymbolAddress((void**)&h_pk,   g_h_pk);
    cudaGetSymbolAddress((void**)&y,      g_y);
    cudaGetSymbolAddress((void**)&Wv_pk,  g_Wv_pk);
    cudaGetSymbolAddress((void**)&Woa_pk, g_Woa_pk);
    cudaGetSymbolAddress((void**)&Wp_pk,  g_Wp_pk);
    cudaGetSymbolAddress((void**)&W1_pk,  g_W1_pk);
    cudaGetSymbolAddress((void**)&W2_pk,  g_W2_pk);
    cudaGetSymbolAddress((void**)&bias_oa,g_bias_oa);

    const int T = TTOK;
    const int TM = (T + BM - 1) / BM;   // 171

    // 0) pack weights (+ concat bias_oa)
    pack_weights<<<(753664 + 384 + 255) / 256, 256>>>(Wv, Wo, Wa, Wp, W1, W2, bo, ba);

    // 1) build q / v_in
    build_qv_kernel<<<TTOK, 256>>>(src, pos, sel_vt, q_pk, vin, vin_pk);

    // 2) value = vin @ Wv^T + bv (masked)
    gemm_bf16<<<dim3(TM, 4), 256>>>(vin_pk, Wv_pk, bv, T, 256, 256,
                                    value, 256, nullptr, nullptr, 0, mask);
    // 3) [off | attn] = q @ [Wo;Wa]^T + [bo;ba]
    gemm_bf16<<<dim3(TM, 6), 256>>>(q_pk, Woa_pk, bias_oa, T, 256, 384,
                                    off, 256, attn, nullptr, 0, nullptr);

    // 4) deformable sampling (softmax fused) -> packed samp
    msdeform_sample_kernel<<<TTOK, 256>>>(value, attn, off, ref, samp_pk);

    // 5) src2 = samp @ Wp^T + bp
    gemm_bf16<<<dim3(TM, 4), 256>>>(samp_pk, Wp_pk, bp, T, 256, 256,
                                    src2, 256, nullptr, nullptr, 0, nullptr);

    // 6) x = LN(vin + src2), also packed
    add_ln_kernel<<<TTOK, 256>>>(vin, src2, g1, be1, x, x_pk, 0);

    // 7) h = relu(x @ W1^T + bf1) -> packed only
    gemm_bf16<<<dim3(TM, 16), 256>>>(x_pk, W1_pk, bf1, T, 256, 1024,
                                     nullptr, 1024, nullptr, h_pk, 1, nullptr);
    // 8) y = h @ W2^T + bf2
    gemm_bf16<<<dim3(TM, 4), 256>>>(h_pk, W2_pk, bf2, T, 1024, 256,
                                    y, 256, nullptr, nullptr, 0, nullptr);

    // 9) out = LN(x + y) scattered into [spatial | all_vt | vt] layout
    add_ln_kernel<<<TTOK, 256>>>(x, y, g2, be2, out, nullptr, 1);

    // 10) all_vt passthrough
    cudaMemcpyAsync(out + (size_t)N_BATCH * LSP * DMODEL, all_vt,
                    (size_t)N_BATCH * NALLVT * DMODEL * sizeof(float),
                    cudaMemcpyDeviceToDevice, 0);
}

// round 8
// speedup vs baseline: 2.0795x; 1.1234x over previous
#include <cuda_runtime.h>
#include <cuda_bf16.h>
#include <math.h>
#include <stdint.h>

#define N_BATCH 4
#define LQ      5448
#define LSP     5440
#define DMODEL  256
#define DFFN    1024
#define NVT     8
#define NALLVT  600
#define TTOK    (N_BATCH * LQ)   // 21792

// -------------------- scratch (planar dual-bf16: hi plane then lo plane) --------------------
__device__ uint32_t g_q_pk   [(size_t)TTOK * DMODEL];        // 2 planes x TTOK*128 words
__device__ float    g_vin    [(size_t)TTOK * DMODEL];
__device__ uint32_t g_vin_pk [(size_t)TTOK * DMODEL];
__device__ float    g_value  [(size_t)TTOK * DMODEL];
__device__ float    g_off    [(size_t)TTOK * DMODEL];
__device__ float    g_attn   [(size_t)TTOK * 128];
__device__ uint32_t g_samp_pk[(size_t)TTOK * DMODEL];
__device__ float    g_src2   [(size_t)TTOK * DMODEL];
__device__ float    g_x      [(size_t)TTOK * DMODEL];
__device__ uint32_t g_x_pk   [(size_t)TTOK * DMODEL];
__device__ uint32_t g_h_pk   [(size_t)TTOK * DFFN];
__device__ float    g_y      [(size_t)TTOK * DMODEL];
// packed weights (planar)
__device__ uint32_t g_Wv_pk [256 * 256];
__device__ uint32_t g_Woa_pk[384 * 256];
__device__ uint32_t g_Wp_pk [256 * 256];
__device__ uint32_t g_W1_pk [1024 * 256];
__device__ uint32_t g_W2_pk [256 * 1024];
__device__ float    g_bias_oa[384];

// ==================== helpers ====================
__device__ __forceinline__ uint32_t smem_u32(const void* p) {
    return (uint32_t)__cvta_generic_to_shared(p);
}
__device__ __forceinline__ void cp_async16(uint32_t dst, const void* src, int src_size) {
    asm volatile("cp.async.cg.shared.global [%0], [%1], 16, %2;\n"
                 :: "r"(dst), "l"(src), "r"(src_size));
}
__device__ __forceinline__ void cp_async_commit() {
    asm volatile("cp.async.commit_group;" ::: "memory");
}
template<int N> __device__ __forceinline__ void cp_async_wait() {
    asm volatile("cp.async.wait_group %0;" :: "n"(N) : "memory");
}
__device__ __forceinline__ void ldm_x4(uint32_t addr, uint32_t& r0, uint32_t& r1,
                                       uint32_t& r2, uint32_t& r3) {
    asm volatile("ldmatrix.sync.aligned.m8n8.x4.shared.b16 {%0,%1,%2,%3}, [%4];"
                 : "=r"(r0), "=r"(r1), "=r"(r2), "=r"(r3) : "r"(addr));
}
__device__ __forceinline__ void mma16(float* d, const uint32_t* a, const uint32_t* b) {
    asm volatile(
        "mma.sync.aligned.m16n8k16.row.col.f32.bf16.bf16.f32 "
        "{%0,%1,%2,%3}, {%4,%5,%6,%7}, {%8,%9}, {%0,%1,%2,%3};"
        : "+f"(d[0]), "+f"(d[1]), "+f"(d[2]), "+f"(d[3])
        : "r"(a[0]), "r"(a[1]), "r"(a[2]), "r"(a[3]), "r"(b[0]), "r"(b[1]));
}
// split two adjacent fp32 into (hi word, lo word), each word = 2 bf16
__device__ __forceinline__ void split2(float vx, float vy, uint32_t& hw, uint32_t& lw) {
    __nv_bfloat16 hx = __float2bfloat16(vx);
    __nv_bfloat16 lx = __float2bfloat16(vx - __bfloat162float(hx));
    __nv_bfloat16 hy = __float2bfloat16(vy);
    __nv_bfloat16 ly = __float2bfloat16(vy - __bfloat162float(hy));
    hw = (uint32_t)__bfloat16_as_ushort(hx) | ((uint32_t)__bfloat16_as_ushort(hy) << 16);
    lw = (uint32_t)__bfloat16_as_ushort(lx) | ((uint32_t)__bfloat16_as_ushort(ly) << 16);
}

// ==================== planar dual-bf16 GEMM via ldmatrix ====================
// out[T,Nout] = A[T,K] * W[Nout,K]^T + bias. KW = K/2 (words per row per plane).
// CTA 128x64, BK = 32 halves (16 words), 8 warps (4M x 2N), warp tile 32x32.
#define BM 128
#define BN 64
#define STR 20              // words per smem row (16 + 4 pad)
#define APL 2560            // A plane words (128*20)
#define BPL 1280            // B plane words (64*20)
#define BUFW 7680           // words per buffer (2*APL + 2*BPL)
#define SMEM_BYTES (2 * BUFW * 4)

__global__ void __launch_bounds__(256, 2)
gemm_pl(const uint32_t* __restrict__ A, size_t psA,
        const uint32_t* __restrict__ Wt, size_t psW,
        const float* __restrict__ bias, int T, int KW, int Nout,
        float* __restrict__ outA, int split, float* __restrict__ outB,
        uint32_t* __restrict__ outPk, size_t psOut,
        int relu, const unsigned char* __restrict__ mask)
{
    extern __shared__ __align__(16) uint32_t smem[];
    const uint32_t sm = smem_u32(smem);

    const int tid  = threadIdx.x;
    const int wid  = tid >> 5;
    const int lane = tid & 31;
    const int bm = blockIdx.x * BM;
    const int bn = blockIdx.y * BN;
    const int mbase = (wid & 3) * 32;
    const int nbase = (wid >> 2) * 32;
    const int gq = lane >> 2;
    const int tg = lane & 3;

    float acc[2][4][4];
#pragma unroll
    for (int mi = 0; mi < 2; mi++)
#pragma unroll
        for (int ni = 0; ni < 4; ni++)
#pragma unroll
            for (int r = 0; r < 4; r++) acc[mi][ni][r] = 0.f;

    auto load = [&](int kw0, int buf) {
        const uint32_t base = sm + buf * (BUFW * 4);
#pragma unroll
        for (int j = 0; j < 4; j++) {              // A: 2 planes x 128 rows x 4 chunks
            int o = tid + 256 * j;
            int plane = o >> 9;
            int oo = o & 511;
            int row = oo >> 2;
            int ch = oo & 3;
            int gr = bm + row;
            const uint32_t* srcp = A + (size_t)plane * psA
                                     + (size_t)(gr < T ? gr : 0) * KW + kw0 + ch * 4;
            cp_async16(base + (plane * APL + row * STR + ch * 4) * 4, srcp, gr < T ? 16 : 0);
        }
#pragma unroll
        for (int j = 0; j < 2; j++) {              // B: 2 planes x 64 rows x 4 chunks
            int o = tid + 256 * j;
            int plane = o >> 8;
            int oo = o & 255;
            int row = oo >> 2;
            int ch = oo & 3;
            const uint32_t* srcp = Wt + (size_t)plane * psW
                                      + (size_t)(bn + row) * KW + kw0 + ch * 4;
            cp_async16(base + (2 * APL + plane * BPL + row * STR + ch * 4) * 4, srcp, 16);
        }
        cp_async_commit();
    };

    const int nch = KW >> 4;
    load(0, 0);

    // ldmatrix per-lane address components
    const int arow = lane & 15;
    const int acol = (lane >> 4) * 4;                          // words
    const int brow = (lane & 7) + ((lane >> 4) & 1) * 8;
    const int bcol = ((lane >> 3) & 1) * 4;                    // words

    for (int i = 0; i < nch; i++) {
        cp_async_wait<0>();
        __syncthreads();
        if (i + 1 < nch) load((i + 1) << 4, (i + 1) & 1);

        const uint32_t base = sm + (i & 1) * (BUFW * 4);
        const uint32_t Ahi = base, Alo = base + APL * 4;
        const uint32_t Bhi = base + 2 * APL * 4, Blo = Bhi + BPL * 4;

#pragma unroll
        for (int k16 = 0; k16 < 2; k16++) {
            const int kw = k16 * 8;
            uint32_t ah[2][4], al[2][4];
#pragma unroll
            for (int mi = 0; mi < 2; mi++) {
                uint32_t off = ((mbase + mi * 16 + arow) * STR + kw + acol) * 4;
                ldm_x4(Ahi + off, ah[mi][0], ah[mi][1], ah[mi][2], ah[mi][3]);
                ldm_x4(Alo + off, al[mi][0], al[mi][1], al[mi][2], al[mi][3]);
            }
            uint32_t bh[4][2], bl[4][2];
#pragma unroll
            for (int hb = 0; hb < 2; hb++) {
                uint32_t off = ((nbase + hb * 16 + brow) * STR + kw + bcol) * 4;
                ldm_x4(Bhi + off, bh[hb*2][0], bh[hb*2][1], bh[hb*2+1][0], bh[hb*2+1][1]);
                ldm_x4(Blo + off, bl[hb*2][0], bl[hb*2][1], bl[hb*2+1][0], bl[hb*2+1][1]);
            }
#pragma unroll
            for (int mi = 0; mi < 2; mi++)
#pragma unroll
                for (int ng = 0; ng < 4; ng++) {
                    mma16(acc[mi][ng], ah[mi], bh[ng]);   // hi*hi
                    mma16(acc[mi][ng], ah[mi], bl[ng]);   // hi*lo
                    mma16(acc[mi][ng], al[mi], bh[ng]);   // lo*hi
                }
        }
        __syncthreads();
    }

    // ---- epilogue ----
    const int wB = Nout - split;
    const int KWout = Nout >> 1;
#pragma unroll
    for (int mi = 0; mi < 2; mi++) {
#pragma unroll
        for (int half = 0; half < 2; half++) {
            int row = bm + mbase + mi * 16 + gq + half * 8;
            if (row >= T) continue;
            bool zero = (mask != nullptr) && (mask[row] != 0);
#pragma unroll
            for (int ni = 0; ni < 4; ni++) {
                int gc = bn + nbase + ni * 8 + tg * 2;
                float vx = acc[mi][ni][half * 2 + 0] + bias[gc];
                float vy = acc[mi][ni][half * 2 + 1] + bias[gc + 1];
                if (relu) { vx = fmaxf(vx, 0.f); vy = fmaxf(vy, 0.f); }
                if (zero) { vx = 0.f; vy = 0.f; }
                if (outPk) {
                    uint32_t hw, lw;
                    split2(vx, vy, hw, lw);
                    size_t wi = (size_t)row * KWout + (gc >> 1);
                    outPk[wi] = hw;
                    outPk[wi + psOut] = lw;
                }
                if (outA) {
                    if (gc < split) {
                        float2 v; v.x = vx; v.y = vy;
                        *reinterpret_cast<float2*>(outA + (size_t)row * split + gc) = v;
                    } else if (outB) {
                        float2 v; v.x = vx; v.y = vy;
                        *reinterpret_cast<float2*>(outB + (size_t)row * wB + (gc - split)) = v;
                    }
                }
            }
        }
    }
}

// -------------------- weight packing (planar) --------------------
#define WV_W  32768
#define WO_W  32768
#define WA_W  16384
#define WP_W  32768
#define W1_W  131072
#define W2_W  131072
#define TOT_W (WV_W + WO_W + WA_W + WP_W + W1_W + W2_W)   // 376832

__global__ void pack_weights(const float* __restrict__ Wv, const float* __restrict__ Wo,
                             const float* __restrict__ Wa, const float* __restrict__ Wp,
                             const float* __restrict__ W1, const float* __restrict__ W2,
                             const float* __restrict__ bo, const float* __restrict__ ba)
{
    int i = blockIdx.x * 256 + threadIdx.x;
    if (i < TOT_W) {
        const float* srcm; uint32_t* dst; int w; size_t ps;
        if (i < WV_W)                      { srcm = Wv; dst = g_Wv_pk;  w = i; ps = WV_W; }
        else if (i < WV_W + WO_W)          { srcm = Wo; dst = g_Woa_pk; w = i - WV_W; ps = WO_W + WA_W; }
        else if (i < WV_W + WO_W + WA_W)   { srcm = Wa; dst = g_Woa_pk + WO_W; w = i - WV_W - WO_W; ps = WO_W + WA_W; }
        else if (i < WV_W + WO_W + WA_W + WP_W)
                                           { srcm = Wp; dst = g_Wp_pk;  w = i - WV_W - WO_W - WA_W; ps = WP_W; }
        else if (i < TOT_W - W2_W)         { srcm = W1; dst = g_W1_pk;  w = i - (WV_W+WO_W+WA_W+WP_W); ps = W1_W; }
        else                               { srcm = W2; dst = g_W2_pk;  w = i - (TOT_W - W2_W); ps = W2_W; }
        float2 v = *reinterpret_cast<const float2*>(srcm + 2 * (size_t)w);
        uint32_t hw, lw;
        split2(v.x, v.y, hw, lw);
        // for Woa, Wa plane offset is relative to combined plane start; dst already offset for hi.
        dst[w] = hw;
        dst[w + ps] = lw;
    } else if (i < TOT_W + 256) {
        g_bias_oa[i - TOT_W] = bo[i - TOT_W];
    } else if (i < TOT_W + 384) {
        g_bias_oa[i - TOT_W] = ba[i - TOT_W - 256];
    }
}

// -------------------- build q / v_in (fp32 + planar packed) --------------------
__global__ void build_qv_kernel(const float* __restrict__ src, const float* __restrict__ pos,
                                const float* __restrict__ sel,
                                uint32_t* __restrict__ q_pk,
                                float* __restrict__ vin, uint32_t* __restrict__ vin_pk)
{
    size_t gid = (size_t)blockIdx.x * 256 + threadIdx.x;     // word index, 2 elems each
    if (gid >= (size_t)TTOK * 128) return;
    int dw = (int)(gid & 127);
    size_t t = gid >> 7;
    int n = (int)(t / LQ);
    int i = (int)(t % LQ);
    float2 sv, pv;
    if (i < LSP) {
        size_t si = ((size_t)n * LSP + i) * DMODEL + dw * 2;
        sv = *reinterpret_cast<const float2*>(src + si);
        pv = *reinterpret_cast<const float2*>(pos + si);
    } else {
        size_t si = ((size_t)n * NVT + (i - LSP)) * DMODEL + dw * 2;
        sv = *reinterpret_cast<const float2*>(sel + si);
        pv.x = 0.f; pv.y = 0.f;
    }
    float qx = sv.x + pv.x, qy = sv.y + pv.y;
    const size_t PS = (size_t)TTOK * 128;
    uint32_t hw, lw;
    split2(qx, qy, hw, lw);
    q_pk[gid] = hw; q_pk[gid + PS] = lw;
    split2(sv.x, sv.y, hw, lw);
    vin_pk[gid] = hw; vin_pk[gid + PS] = lw;
    *reinterpret_cast<float2*>(vin + 2 * gid) = sv;
}

// -------------------- deformable sampling: warp per (token, head) --------------------
__global__ void msdeform_sample_kernel(const float* __restrict__ value,
                                       const float* __restrict__ logits,
                                       const float* __restrict__ off,
                                       const float* __restrict__ ref,
                                       uint32_t* __restrict__ out_pk)
{
    const int nq   = blockIdx.x;
    const int n    = nq / LQ;
    const int m    = threadIdx.x >> 5;
    const int lane = threadIdx.x & 31;

    const float* lg = logits + (size_t)nq * 128 + m * 16;
    float v = (lane < 16) ? lg[lane] : -1e30f;
    float mx = v;
#pragma unroll
    for (int o = 16; o > 0; o >>= 1) mx = fmaxf(mx, __shfl_xor_sync(0xffffffffu, mx, o));
    float e = (lane < 16) ? __expf(v - mx) : 0.f;
    float sm = e;
#pragma unroll
    for (int o = 16; o > 0; o >>= 1) sm += __shfl_xor_sync(0xffffffffu, sm, o);
    float wgt = e / sm;

    float offv = off[(size_t)nq * DMODEL + m * 32 + lane];
    float refv = (lane < 8) ? ref[(size_t)nq * 8 + lane] : 0.f;

    const float* vb = value + (size_t)n * LQ * DMODEL + m * 32 + lane;

    const int HH[4] = {64, 32, 16, 8};
    const int WW[4] = {64, 32, 16, 8};
    const int ST[4] = {0, 4096, 5120, 5376};

    float acc = 0.f;
#pragma unroll
    for (int s = 0; s < 16; s++) {
        const int l = s >> 2;
        float dx = __shfl_sync(0xffffffffu, offv, 2 * s);
        float dy = __shfl_sync(0xffffffffu, offv, 2 * s + 1);
        float rx = __shfl_sync(0xffffffffu, refv, 2 * l);
        float ry = __shfl_sync(0xffffffffu, refv, 2 * l + 1);
        float ws = __shfl_sync(0xffffffffu, wgt, s);
        const int H = HH[l], W = WW[l], st = ST[l];

        float x = rx * (float)W + dx - 0.5f;
        float y = ry * (float)H + dy - 0.5f;
        float xf = floorf(x), yf = floorf(y);
        int x0 = (int)xf, y0 = (int)yf;
        float wx = x - xf, wy = y - yf;

        float w00 = (1.f - wx) * (1.f - wy);
        float w10 = wx * (1.f - wy);
        float w01 = (1.f - wx) * wy;
        float w11 = wx * wy;

        float samp = 0.f;
        if (x0 >= 0 && x0 < W && y0 >= 0 && y0 < H)
            samp += w00 * vb[(size_t)(st + y0 * W + x0) * DMODEL];
        if (x0 + 1 >= 0 && x0 + 1 < W && y0 >= 0 && y0 < H)
            samp += w10 * vb[(size_t)(st + y0 * W + x0 + 1) * DMODEL];
        if (x0 >= 0 && x0 < W && y0 + 1 >= 0 && y0 + 1 < H)
            samp += w01 * vb[(size_t)(st + (y0 + 1) * W + x0) * DMODEL];
        if (x0 + 1 >= 0 && x0 + 1 < W && y0 + 1 >= 0 && y0 + 1 < H)
            samp += w11 * vb[(size_t)(st + (y0 + 1) * W + x0 + 1) * DMODEL];

        acc += ws * samp;
    }
    // planar packed write: even lanes pack (acc, acc_{lane+1})
    float accn = __shfl_down_sync(0xffffffffu, acc, 1);
    if ((lane & 1) == 0) {
        uint32_t hw, lw;
        split2(acc, accn, hw, lw);
        size_t wi = (size_t)nq * 128 + ((m * 32 + lane) >> 1);
        out_pk[wi] = hw;
        out_pk[wi + (size_t)TTOK * 128] = lw;
    }
}

// -------------------- add + LayerNorm --------------------
__global__ void add_ln_kernel(const float* __restrict__ a, const float* __restrict__ b,
                              const float* __restrict__ g, const float* __restrict__ beta,
                              float* __restrict__ out, uint32_t* __restrict__ out_pk, int scatter)
{
    const int t = blockIdx.x;
    const int d = threadIdx.x;
    const int lane = d & 31, wid = d >> 5;

    float v = a[(size_t)t * DMODEL + d] + b[(size_t)t * DMODEL + d];

    __shared__ float red[8];
    float s = v;
#pragma unroll
    for (int o = 16; o > 0; o >>= 1) s += __shfl_xor_sync(0xffffffffu, s, o);
    if (lane == 0) red[wid] = s;
    __syncthreads();
    float mean;
    {
        if (d == 0) {
            float tot = 0.f;
#pragma unroll
            for (int i = 0; i < 8; i++) tot += red[i];
            red[0] = tot;
        }
        __syncthreads();
        mean = red[0] * (1.f / 256.f);
    }
    __syncthreads();

    float xc = v - mean;
    s = xc * xc;
#pragma unroll
    for (int o = 16; o > 0; o >>= 1) s += __shfl_xor_sync(0xffffffffu, s, o);
    if (lane == 0) red[wid] = s;
    __syncthreads();
    float var;
    {
        if (d == 0) {
            float tot = 0.f;
#pragma unroll
            for (int i = 0; i < 8; i++) tot += red[i];
            red[0] = tot;
        }
        __syncthreads();
        var = red[0] * (1.f / 256.f);
    }

    float r = g[d] * xc * rsqrtf(var + 1e-5f) + beta[d];

    if (out_pk) {
        float rn = __shfl_down_sync(0xffffffffu, r, 1);
        if ((d & 1) == 0) {
            uint32_t hw, lw;
            split2(r, rn, hw, lw);
            size_t wi = (size_t)t * 128 + (d >> 1);
            out_pk[wi] = hw;
            out_pk[wi + (size_t)TTOK * 128] = lw;
        }
    }

    float* dst;
    if (!scatter) {
        dst = out + (size_t)t * DMODEL;
    } else {
        int n = t / LQ, i = t % LQ;
        if (i < LSP)
            dst = out + ((size_t)n * LSP + i) * DMODEL;
        else
            dst = out + ((size_t)N_BATCH * LSP + (size_t)N_BATCH * NALLVT) * DMODEL
                      + ((size_t)n * NVT + (i - LSP)) * DMODEL;
    }
    dst[d] = r;
}

// -------------------- launch --------------------
extern "C" void kernel_launch(void* const* d_in, const int* in_sizes, int n_in,
                              void* d_out, int out_size)
{
    const float* src  = (const float*)d_in[0];
    const float* pos  = (const float*)d_in[1];
    const float* ref  = (const float*)d_in[2];
    const unsigned char* mask = (const unsigned char*)d_in[5];
    const float* all_vt = (const float*)d_in[6];
    const float* sel_vt = (const float*)d_in[7];
    const float* Wv = (const float*)d_in[8];   const float* bv  = (const float*)d_in[9];
    const float* Wo = (const float*)d_in[10];  const float* bo  = (const float*)d_in[11];
    const float* Wa = (const float*)d_in[12];  const float* ba  = (const float*)d_in[13];
    const float* Wp = (const float*)d_in[14];  const float* bp  = (const float*)d_in[15];
    const float* g1 = (const float*)d_in[16];  const float* be1 = (const float*)d_in[17];
    const float* W1 = (const float*)d_in[18];  const float* bf1 = (const float*)d_in[19];
    const float* W2 = (const float*)d_in[20];  const float* bf2 = (const float*)d_in[21];
    const float* g2 = (const float*)d_in[22];  const float* be2 = (const float*)d_in[23];
    float* out = (float*)d_out;

    uint32_t *q_pk, *vin_pk, *samp_pk, *x_pk, *h_pk;
    uint32_t *Wv_pk, *Woa_pk, *Wp_pk, *W1_pk, *W2_pk;
    float *vin, *value, *off, *attn, *src2, *x, *y, *bias_oa;
    cudaGetSymbolAddress((void**)&q_pk,   g_q_pk);
    cudaGetSymbolAddress((void**)&vin,    g_vin);
    cudaGetSymbolAddress((void**)&vin_pk, g_vin_pk);
    cudaGetSymbolAddress((void**)&value,  g_value);
    cudaGetSymbolAddress((void**)&off,    g_off);
    cudaGetSymbolAddress((void**)&attn,   g_attn);
    cudaGetSymbolAddress((void**)&samp_pk,g_samp_pk);
    cudaGetSymbolAddress((void**)&src2,   g_src2);
    cudaGetSymbolAddress((void**)&x,      g_x);
    cudaGetSymbolAddress((void**)&x_pk,   g_x_pk);
    cudaGetSymbolAddress((void**)&h_pk,   g_h_pk);
    cudaGetSymbolAddress((void**)&y,      g_y);
    cudaGetSymbolAddress((void**)&Wv_pk,  g_Wv_pk);
    cudaGetSymbolAddress((void**)&Woa_pk, g_Woa_pk);
    cudaGetSymbolAddress((void**)&Wp_pk,  g_Wp_pk);
    cudaGetSymbolAddress((void**)&W1_pk,  g_W1_pk);
    cudaGetSymbolAddress((void**)&W2_pk,  g_W2_pk);
    cudaGetSymbolAddress((void**)&bias_oa,g_bias_oa);

    cudaFuncSetAttribute(gemm_pl, cudaFuncAttributeMaxDynamicSharedMemorySize, SMEM_BYTES);

    const int T = TTOK;
    const int TM = (T + BM - 1) / BM;   // 171
    const size_t psAct = (size_t)TTOK * 128;   // activation plane words (K=256)
    const size_t psH   = (size_t)TTOK * 512;   // h plane words (K=1024)

    // 0) pack weights (+ concat bias_oa)
    pack_weights<<<(TOT_W + 384 + 255) / 256, 256>>>(Wv, Wo, Wa, Wp, W1, W2, bo, ba);

    // 1) build q / v_in
    build_qv_kernel<<<(TTOK * 128 + 255) / 256, 256>>>(src, pos, sel_vt, q_pk, vin, vin_pk);

    // 2) value = vin @ Wv^T + bv (masked)
    gemm_pl<<<dim3(TM, 4), 256, SMEM_BYTES>>>(vin_pk, psAct, Wv_pk, WV_W, bv, T, 128, 256,
                                              value, 256, nullptr, nullptr, 0, 0, mask);
    // 3) [off | attn] = q @ [Wo;Wa]^T + [bo;ba]
    gemm_pl<<<dim3(TM, 6), 256, SMEM_BYTES>>>(q_pk, psAct, Woa_pk, WO_W + WA_W, bias_oa, T, 128, 384,
                                              off, 256, attn, nullptr, 0, 0, nullptr);

    // 4) deformable sampling (softmax fused) -> planar packed samp
    msdeform_sample_kernel<<<TTOK, 256>>>(value, attn, off, ref, samp_pk);

    // 5) src2 = samp @ Wp^T + bp
    gemm_pl<<<dim3(TM, 4), 256, SMEM_BYTES>>>(samp_pk, psAct, Wp_pk, WP_W, bp, T, 128, 256,
                                              src2, 256, nullptr, nullptr, 0, 0, nullptr);

    // 6) x = LN(vin + src2), also planar packed
    add_ln_kernel<<<TTOK, 256>>>(vin, src2, g1, be1, x, x_pk, 0);

    // 7) h = relu(x @ W1^T + bf1) -> planar packed only
    gemm_pl<<<dim3(TM, 16), 256, SMEM_BYTES>>>(x_pk, psAct, W1_pk, W1_W, bf1, T, 128, 1024,
                                               nullptr, 1024, nullptr, h_pk, psH, 1, nullptr);
    // 8) y = h @ W2^T + bf2
    gemm_pl<<<dim3(TM, 4), 256, SMEM_BYTES>>>(h_pk, psH, W2_pk, W2_W, bf2, T, 512, 256,
                                              y, 256, nullptr, nullptr, 0, 0, nullptr);

    // 9) out = LN(x + y) scattered into [spatial | all_vt | vt] layout
    add_ln_kernel<<<TTOK, 256>>>(x, y, g2, be2, out, nullptr, 1);

    // 10) all_vt passthrough
    cudaMemcpyAsync(out + (size_t)N_BATCH * LSP * DMODEL, all_vt,
                    (size_t)N_BATCH * NALLVT * DMODEL * sizeof(float),
                    cudaMemcpyDeviceToDevice, 0);
}